// round 1
// baseline (speedup 1.0000x reference)
#include <cuda_runtime.h>
#include <math.h>

#define NN  384
#define DIM 512
#define NH  8
#define NF  64

// ---------------- scratch (device globals; no allocation allowed) ----------
__device__ float g_gl[NN * DIM];
__device__ float g_gr[NN * DIM];
__device__ float g_c[2 * NH * NN];   // [which(l=0,r=1)][h][n] : sum_f a[f]*g[n,h,f]
__device__ float g_x1[NN * DIM];     // layer-0 output / layer-1 input

// ---------------- GEMM: O[384,512] = X[384,512] @ W[512,512] ----------------
#define BM 32
#define BN 64
#define BK 16

__global__ void gemm_kernel(const float* __restrict__ Xp,
                            const float* __restrict__ Wl,
                            const float* __restrict__ Wr,
                            int use_x1) {
    const float* X = use_x1 ? g_x1 : Xp;
    const float* W = blockIdx.z ? Wr : Wl;
    float* O       = blockIdx.z ? g_gr : g_gl;

    __shared__ float As[BM][BK];
    __shared__ float Bs[BK][BN + 4];

    int tid = threadIdx.x;
    int tx = tid & 15, ty = tid >> 4;
    int m0 = blockIdx.y * BM, n0 = blockIdx.x * BN;

    float c[2][4];
#pragma unroll
    for (int i = 0; i < 2; i++)
#pragma unroll
        for (int j = 0; j < 4; j++) c[i][j] = 0.f;

    for (int k0 = 0; k0 < DIM; k0 += BK) {
        {   // As: 32x16 floats, 2 per thread
            int m = tid >> 3, kq = tid & 7;
            float2 v = *(const float2*)&X[(m0 + m) * DIM + k0 + kq * 2];
            As[m][kq * 2] = v.x;
            As[m][kq * 2 + 1] = v.y;
        }
        {   // Bs: 16x64 floats, 4 per thread
            int k = tid >> 4, nq = tid & 15;
            *(float4*)&Bs[k][nq * 4] =
                *(const float4*)&W[(k0 + k) * DIM + n0 + nq * 4];
        }
        __syncthreads();
#pragma unroll
        for (int k = 0; k < BK; k++) {
            float a0 = As[ty * 2][k];
            float a1 = As[ty * 2 + 1][k];
            float4 b = *(const float4*)&Bs[k][tx * 4];
            c[0][0] = fmaf(a0, b.x, c[0][0]);
            c[0][1] = fmaf(a0, b.y, c[0][1]);
            c[0][2] = fmaf(a0, b.z, c[0][2]);
            c[0][3] = fmaf(a0, b.w, c[0][3]);
            c[1][0] = fmaf(a1, b.x, c[1][0]);
            c[1][1] = fmaf(a1, b.y, c[1][1]);
            c[1][2] = fmaf(a1, b.z, c[1][2]);
            c[1][3] = fmaf(a1, b.w, c[1][3]);
        }
        __syncthreads();
    }
#pragma unroll
    for (int il = 0; il < 2; il++) {
        float4 r = make_float4(c[il][0], c[il][1], c[il][2], c[il][3]);
        *(float4*)&O[(m0 + ty * 2 + il) * DIM + n0 + tx * 4] = r;
    }
}

// ------------- c vectors: c[which][h][n] = sum_f a[f] * g[n, h*64+f] --------
__global__ void compute_c_kernel(const float* __restrict__ a) {
    int n = blockIdx.x;
    const float* g = blockIdx.y ? g_gr : g_gl;
    float* c = g_c + blockIdx.y * (NH * NN);
    int w = threadIdx.x >> 5, lane = threadIdx.x & 31;   // warp = head
    float v = a[lane]      * g[n * DIM + w * NF + lane]
            + a[lane + 32] * g[n * DIM + w * NF + lane + 32];
#pragma unroll
    for (int o = 16; o; o >>= 1) v += __shfl_xor_sync(~0u, v, o);
    if (lane == 0) c[w * NN + n] = v;
}

// ---------------- fused attention: scores + softmax + aggregate + residual --
#define TI  16                 // i-rows per block
#define JT  32                 // j per warp pass (= lanes)
#define NJT (NN / JT)          // 12
#define FC  8                  // f chunk
#define NFC (NF / FC)          // 8

__global__ void attn_kernel(const float* __restrict__ a,
                            const int* __restrict__ adj,
                            const float* __restrict__ x_in_p,
                            float* __restrict__ x_out_p,
                            int mode) {               // 0: layer0 (ELU), 1: layer1
    __shared__ float gl8[NN][FC + 1];      // 13824 B
    __shared__ float att_s[TI][NN];        // 24576 B
    __shared__ float gr_s[JT][NF + 4];     //  8704 B
    __shared__ float cl_s[NN];             //  1536 B
    __shared__ float cr_s[TI];             //    64 B
    __shared__ float a4_s[NF];             //   256 B   total 48960 B < 48KB

    const float* x_in = mode ? g_x1 : x_in_p;
    float* x_out      = mode ? x_out_p : g_x1;

    int h = blockIdx.y;
    int i0 = blockIdx.x * TI;
    int tid = threadIdx.x;
    int lane = tid & 31, w = tid >> 5;
    int il0 = w * 2;                       // this warp handles i0+il0, i0+il0+1

    if (tid < NF) a4_s[tid] = 0.4f * a[tid];
    for (int j = tid; j < NN; j += 256) cl_s[j] = 0.6f * g_c[h * NN + j];
    if (tid < TI) cr_s[tid] = 0.6f * g_c[NH * NN + h * NN + i0 + tid];

    float acc[2][NJT];
#pragma unroll
    for (int il = 0; il < 2; il++)
#pragma unroll
        for (int jt = 0; jt < NJT; jt++) acc[il][jt] = 0.f;

    // -------- phase 1: acc[i][j] = sum_f 0.4*a[f]*|g_r[i,f]+g_l[j,f]| ------
    for (int fc = 0; fc < NFC; fc++) {
        for (int t = tid; t < NN * FC; t += 256) {
            int j = t >> 3, f8 = t & 7;
            gl8[j][f8] = g_gl[j * DIM + h * NF + fc * FC + f8];
        }
        __syncthreads();   // also covers a4_s/cl_s/cr_s on first iteration

        float a_r[FC];
#pragma unroll
        for (int f8 = 0; f8 < FC; f8++) a_r[f8] = a4_s[fc * FC + f8];
        float gr_r[2][FC];
#pragma unroll
        for (int il = 0; il < 2; il++)
#pragma unroll
            for (int f8 = 0; f8 < FC; f8++)
                gr_r[il][f8] = g_gr[(i0 + il0 + il) * DIM + h * NF + fc * FC + f8];

#pragma unroll
        for (int jt = 0; jt < NJT; jt++) {
            int j = jt * JT + lane;
#pragma unroll
            for (int f8 = 0; f8 < FC; f8++) {
                float gl = gl8[j][f8];
#pragma unroll
                for (int il = 0; il < 2; il++) {
                    float s  = gr_r[il][f8] + gl;
                    float sa = __int_as_float(__float_as_int(s) & 0x7fffffff);
                    acc[il][jt] = fmaf(a_r[f8], sa, acc[il][jt]);
                }
            }
        }
        __syncthreads();
    }

    // -------- masked softmax over j (per warp, two rows) --------------------
#pragma unroll
    for (int il = 0; il < 2; il++) {
        int i = i0 + il0 + il;
        float cr = cr_s[il0 + il];
        float m = -1e30f;
        unsigned vmask = 0;
#pragma unroll
        for (int jt = 0; jt < NJT; jt++) {
            int j = jt * JT + lane;
            int av = adj[i * NN + j];
            bool valid = (av != 0) || (j == i);
            float e = cr + cl_s[j] + acc[il][jt];
            acc[il][jt] = e;
            if (valid) { vmask |= (1u << jt); m = fmaxf(m, e); }
        }
#pragma unroll
        for (int o = 16; o; o >>= 1) m = fmaxf(m, __shfl_xor_sync(~0u, m, o));
        float sum = 0.f;
#pragma unroll
        for (int jt = 0; jt < NJT; jt++) {
            float p = ((vmask >> jt) & 1) ? __expf(acc[il][jt] - m) : 0.f;
            acc[il][jt] = p;
            sum += p;
        }
#pragma unroll
        for (int o = 16; o; o >>= 1) sum += __shfl_xor_sync(~0u, sum, o);
        float inv = 1.f / sum;
#pragma unroll
        for (int jt = 0; jt < NJT; jt++)
            att_s[il0 + il][jt * JT + lane] = acc[il][jt] * inv;
    }
    __syncthreads();

    // -------- phase 2: out[i,f] = sum_j att[i,j] * g_r[j,f] -----------------
    float o00 = 0.f, o01 = 0.f, o10 = 0.f, o11 = 0.f;
    for (int jt0 = 0; jt0 < NJT; jt0++) {
        {
            int j = tid >> 3, fq = tid & 7;
            const float* src = &g_gr[(jt0 * JT + j) * DIM + h * NF + fq * 8];
            *(float4*)&gr_s[j][fq * 8]     = *(const float4*)src;
            *(float4*)&gr_s[j][fq * 8 + 4] = *(const float4*)(src + 4);
        }
        __syncthreads();
#pragma unroll 8
        for (int jj = 0; jj < JT; jj++) {
            float at0 = att_s[il0][jt0 * JT + jj];
            float at1 = att_s[il0 + 1][jt0 * JT + jj];
            float2 g = *(const float2*)&gr_s[jj][lane * 2];
            o00 = fmaf(at0, g.x, o00);
            o01 = fmaf(at0, g.y, o01);
            o10 = fmaf(at1, g.x, o10);
            o11 = fmaf(at1, g.y, o11);
        }
        __syncthreads();
    }

    // -------- epilogue: activation + residual -------------------------------
    {
        int col = h * NF + lane * 2;
#pragma unroll
        for (int il = 0; il < 2; il++) {
            int i = i0 + il0 + il;
            float v0 = il ? o10 : o00;
            float v1 = il ? o11 : o01;
            if (mode == 0) {   // ELU (alpha=1)
                v0 = v0 > 0.f ? v0 : expm1f(v0);
                v1 = v1 > 0.f ? v1 : expm1f(v1);
            }
            float2 xi = *(const float2*)&x_in[i * DIM + col];
            float2 r;
            r.x = xi.x + v0;
            r.y = xi.y + v1;
            *(float2*)&x_out[i * DIM + col] = r;
        }
    }
}

// ---------------------------------------------------------------------------
extern "C" void kernel_launch(void* const* d_in, const int* in_sizes, int n_in,
                              void* d_out, int out_size) {
    const float* x   = (const float*)d_in[0];
    const int*   adj = (const int*)  d_in[1];
    const float* Wl0 = (const float*)d_in[2];
    const float* Wr0 = (const float*)d_in[3];
    const float* a0  = (const float*)d_in[4];
    const float* Wl1 = (const float*)d_in[5];
    const float* Wr1 = (const float*)d_in[6];
    const float* a1  = (const float*)d_in[7];
    float* out = (float*)d_out;

    dim3 gg(DIM / BN, NN / BM, 2);   // (8, 12, 2)
    dim3 gc(NN, 2);                  // (384, 2)
    dim3 ga(NN / TI, NH);            // (24, 8)

    // layer 0
    gemm_kernel<<<gg, 256>>>(x, Wl0, Wr0, 0);
    compute_c_kernel<<<gc, 256>>>(a0);
    attn_kernel<<<ga, 256>>>(a0, adj, x, out, 0);    // writes g_x1 (ELU + residual)
    // layer 1
    gemm_kernel<<<gg, 256>>>(x, Wl1, Wr1, 1);
    compute_c_kernel<<<gc, 256>>>(a1);
    attn_kernel<<<ga, 256>>>(a1, adj, x, out, 1);    // writes d_out (residual)
}

// round 2
// speedup vs baseline: 1.0705x; 1.0705x over previous
#include <cuda_runtime.h>
#include <math.h>

#define NN  384
#define DIM 512
#define NH  8
#define NF  64

typedef unsigned long long ull;

// ---------------- packed f32x2 helpers ----------------
__device__ __forceinline__ ull bcast2(float s) {
    ull r; asm("mov.b64 %0, {%1, %1};" : "=l"(r) : "f"(s)); return r;
}
__device__ __forceinline__ void unpack2(ull v, float& lo, float& hi) {
    asm("mov.b64 {%0, %1}, %2;" : "=f"(lo), "=f"(hi) : "l"(v));
}
__device__ __forceinline__ ull fma2(ull a, ull b, ull c) {
    ull d; asm("fma.rn.f32x2 %0, %1, %2, %3;" : "=l"(d) : "l"(a), "l"(b), "l"(c));
    return d;
}
__device__ __forceinline__ ull add2(ull a, ull b) {
    ull d; asm("add.rn.f32x2 %0, %1, %2;" : "=l"(d) : "l"(a), "l"(b));
    return d;
}
__device__ __forceinline__ ull abs2(ull v) { return v & 0x7FFFFFFF7FFFFFFFULL; }

// ---------------- scratch (device globals) ----------------
__device__ float g_gl[NN * DIM];
__device__ float g_gr[NN * DIM];
__device__ float g_c[2 * NH * NN];   // [which(l=0,r=1)][h][n]
__device__ float g_x1[NN * DIM];     // layer-0 output / layer-1 input

// =================== GEMM + fused c-vector epilogue ===================
// O[384,512] = X[384,512] @ W[512,512];  c[n] = sum_f a[f]*O[n, h*64+f]
#define BM 32
#define BN 64
#define BK 32

__global__ void __launch_bounds__(256)
gemm_kernel(const float* __restrict__ Xp,
            const float* __restrict__ Wl,
            const float* __restrict__ Wr,
            const float* __restrict__ av,
            int use_x1) {
    const float* X = use_x1 ? g_x1 : Xp;
    const float* W = blockIdx.z ? Wr : Wl;
    float* O       = blockIdx.z ? g_gr : g_gl;
    float* cvec    = g_c + blockIdx.z * (NH * NN) + blockIdx.x * NN; // h = blockIdx.x

    __shared__ float2 As2[BK][BM + 1];   // duplicated pairs (v,v), transposed
    __shared__ float  Bs[BK][BN];

    int tid = threadIdx.x;
    int tx = tid & 15, ty = tid >> 4;
    int m0 = blockIdx.y * BM, n0 = blockIdx.x * BN;

    ull acc00 = 0, acc01 = 0, acc10 = 0, acc11 = 0;

    int mX = tid >> 3, kqX = tid & 7;       // X loader: row, k-quad
    int kW = tid >> 3, nW = (tid & 7) * 8;  // W loader: k-row, 8 cols

    const float* xptr = X + (m0 + mX) * DIM + kqX * 4;
    const float* wptr = W + kW * DIM + n0 + nW;

    float4 xbuf  = *(const float4*)xptr;
    float4 wbuf0 = *(const float4*)wptr;
    float4 wbuf1 = *(const float4*)(wptr + 4);

    const int NT = DIM / BK;
    for (int t = 0; t < NT; t++) {
        // stage current tile to smem
        As2[kqX * 4 + 0][mX] = make_float2(xbuf.x, xbuf.x);
        As2[kqX * 4 + 1][mX] = make_float2(xbuf.y, xbuf.y);
        As2[kqX * 4 + 2][mX] = make_float2(xbuf.z, xbuf.z);
        As2[kqX * 4 + 3][mX] = make_float2(xbuf.w, xbuf.w);
        *(float4*)&Bs[kW][nW]     = wbuf0;
        *(float4*)&Bs[kW][nW + 4] = wbuf1;
        __syncthreads();

        // prefetch next tile into registers (overlaps with compute)
        if (t + 1 < NT) {
            xbuf  = *(const float4*)(xptr + (t + 1) * BK);
            wbuf0 = *(const float4*)(wptr + (t + 1) * BK * DIM);
            wbuf1 = *(const float4*)(wptr + (t + 1) * BK * DIM + 4);
        }

#pragma unroll
        for (int k = 0; k < BK; k++) {
            ull pa0 = *(const ull*)&As2[k][ty * 2];
            ull pa1 = *(const ull*)&As2[k][ty * 2 + 1];
            ulonglong2 bp = *(const ulonglong2*)&Bs[k][tx * 4];
            acc00 = fma2(pa0, bp.x, acc00);
            acc01 = fma2(pa0, bp.y, acc01);
            acc10 = fma2(pa1, bp.x, acc10);
            acc11 = fma2(pa1, bp.y, acc11);
        }
        __syncthreads();
    }

    // epilogue: unpack, store O, fused c-vector partial + warp reduce
    float v00, v01, v02, v03, v10, v11, v12, v13;
    unpack2(acc00, v00, v01); unpack2(acc01, v02, v03);
    unpack2(acc10, v10, v11); unpack2(acc11, v12, v13);

    int row0 = m0 + ty * 2;
    *(float4*)&O[row0 * DIM + n0 + tx * 4]       = make_float4(v00, v01, v02, v03);
    *(float4*)&O[(row0 + 1) * DIM + n0 + tx * 4] = make_float4(v10, v11, v12, v13);

    float4 af = *(const float4*)&av[tx * 4];     // f = local col
    float cp0 = fmaf(af.x, v00, fmaf(af.y, v01, fmaf(af.z, v02, af.w * v03)));
    float cp1 = fmaf(af.x, v10, fmaf(af.y, v11, fmaf(af.z, v12, af.w * v13)));
#pragma unroll
    for (int o = 1; o < 16; o <<= 1) {
        cp0 += __shfl_xor_sync(0xffffffffu, cp0, o);
        cp1 += __shfl_xor_sync(0xffffffffu, cp1, o);
    }
    if (tx == 0) {
        cvec[row0]     = cp0;
        cvec[row0 + 1] = cp1;
    }
}

// =================== fused attention ===================
#define TI  16
#define GLS (NN + 4)        // glT row stride (floats)
#define ATS (TI + 2)        // att_t row stride

__global__ void __launch_bounds__(256)
attn_kernel(const float* __restrict__ a,
            const int* __restrict__ adj,
            const float* __restrict__ x_in_p,
            float* __restrict__ x_out_p,
            int mode) {                      // 0: layer0 (ELU), 1: layer1
    __shared__ float  att_t[NN][ATS];        // 27648 B (transposed attention)
    __shared__ float  sbuf[8 * GLS];         // 12416 B (glT in p1 / gr_s in p2)
    __shared__ float  cl_s[NN];              //  1536 B
    __shared__ float2 grdup[TI][8];          //  1024 B (duplicated g_r chunk)
    __shared__ float2 a4d[NF];               //   512 B (duplicated 0.4*a)
    __shared__ float  cr_s[TI];              //    64 B  -> total ~43.2 KB

    const float* x_in = mode ? g_x1 : x_in_p;
    float* x_out      = mode ? x_out_p : g_x1;

    int h = blockIdx.y;
    int i0 = blockIdx.x * TI;
    int tid = threadIdx.x, lane = tid & 31, w = tid >> 5;
    int il0 = w * 2;                  // warp owns rows i0+il0, i0+il0+1
    int jbase = 2 * lane;             // lane owns j pairs {64jt+2L, +1}

    if (tid < NF) { float t4 = 0.4f * a[tid]; a4d[tid] = make_float2(t4, t4); }
    for (int j = tid; j < NN; j += 256) cl_s[j] = 0.6f * g_c[h * NN + j];
    if (tid < TI) cr_s[tid] = 0.6f * g_c[NH * NN + h * NN + i0 + tid];

    ull acc2[2][6];
#pragma unroll
    for (int il = 0; il < 2; il++)
#pragma unroll
        for (int jt = 0; jt < 6; jt++) acc2[il][jt] = 0ULL;

    // ---- phase 1: acc[i][jpair] += 0.4a[f] * |g_r[i,f] + g_l[j,f]| ----
    for (int fc = 0; fc < 8; fc++) {
#pragma unroll
        for (int it = 0; it < 6; it++) {            // fill glT (transposed)
            int idx = tid + 256 * it;               // 0..1535 float2s
            int fp = idx & 3, j = idx >> 2;
            float2 v = *(const float2*)&g_gl[j * DIM + h * NF + fc * 8 + fp * 2];
            sbuf[(fp * 2) * GLS + j]     = v.x;
            sbuf[(fp * 2 + 1) * GLS + j] = v.y;
        }
        if (tid < TI * 8) {                          // fill grdup
            int ii = tid >> 3, f8 = tid & 7;
            float v = g_gr[(i0 + ii) * DIM + h * NF + fc * 8 + f8];
            grdup[ii][f8] = make_float2(v, v);
        }
        __syncthreads();
#pragma unroll
        for (int f8 = 0; f8 < 8; f8++) {
            ull paf = *(const ull*)&a4d[fc * 8 + f8];
            ull pg0 = *(const ull*)&grdup[il0][f8];
            ull pg1 = *(const ull*)&grdup[il0 + 1][f8];
#pragma unroll
            for (int jt = 0; jt < 6; jt++) {
                ull gl2 = *(const ull*)&sbuf[f8 * GLS + jt * 64 + jbase];
                acc2[0][jt] = fma2(paf, abs2(add2(pg0, gl2)), acc2[0][jt]);
                acc2[1][jt] = fma2(paf, abs2(add2(pg1, gl2)), acc2[1][jt]);
            }
        }
        __syncthreads();
    }

    // ---- masked softmax over j (per warp, two rows) ----
    float2 clp[6];
#pragma unroll
    for (int jt = 0; jt < 6; jt++) clp[jt] = *(const float2*)&cl_s[jt * 64 + jbase];

#pragma unroll
    for (int il = 0; il < 2; il++) {
        int i = i0 + il0 + il;
        float cr = cr_s[il0 + il];
        float e[12];
        unsigned vm = 0;
        float m = -1e30f;
#pragma unroll
        for (int jt = 0; jt < 6; jt++) {
            float u0, u1; unpack2(acc2[il][jt], u0, u1);
            int j0 = jt * 64 + jbase;
            int2 adv = *(const int2*)&adj[i * NN + j0];
            float e0 = cr + clp[jt].x + u0;
            float e1 = cr + clp[jt].y + u1;
            e[jt * 2] = e0; e[jt * 2 + 1] = e1;
            if (adv.x || (j0 == i))     { vm |= 1u << (jt * 2);     m = fmaxf(m, e0); }
            if (adv.y || (j0 + 1 == i)) { vm |= 1u << (jt * 2 + 1); m = fmaxf(m, e1); }
        }
#pragma unroll
        for (int o = 16; o; o >>= 1) m = fmaxf(m, __shfl_xor_sync(0xffffffffu, m, o));
        float sum = 0.f;
#pragma unroll
        for (int q = 0; q < 12; q++) {
            float p = ((vm >> q) & 1) ? __expf(e[q] - m) : 0.f;
            e[q] = p; sum += p;
        }
#pragma unroll
        for (int o = 16; o; o >>= 1) sum += __shfl_xor_sync(0xffffffffu, sum, o);
        float inv = 1.f / sum;
#pragma unroll
        for (int jt = 0; jt < 6; jt++) {
            att_t[jt * 64 + jbase][il0 + il]     = e[jt * 2] * inv;
            att_t[jt * 64 + jbase + 1][il0 + il] = e[jt * 2 + 1] * inv;
        }
    }
    __syncthreads();

    // ---- phase 2: out[i, fpair] = sum_j att[i,j] * g_r[j, fpair] ----
    ull o0 = 0, o1 = 0;
    float* gr_s = sbuf;                 // reuse as [32][68]
    for (int jt0 = 0; jt0 < 12; jt0++) {
        {
            int jr = tid >> 3, fq = tid & 7;
            const float4* src = (const float4*)&g_gr[(jt0 * 32 + jr) * DIM + h * NF + fq * 8];
            *(float4*)&gr_s[jr * 68 + fq * 8]     = src[0];
            *(float4*)&gr_s[jr * 68 + fq * 8 + 4] = src[1];
        }
        __syncthreads();
#pragma unroll
        for (int jj = 0; jj < 32; jj++) {
            float2 ap = *(const float2*)&att_t[jt0 * 32 + jj][il0];
            ull gp = *(const ull*)&gr_s[jj * 68 + jbase];
            o0 = fma2(bcast2(ap.x), gp, o0);
            o1 = fma2(bcast2(ap.y), gp, o1);
        }
        __syncthreads();
    }

    // ---- epilogue: activation + residual ----
    {
        int col = h * NF + jbase;
        float r00, r01, r10, r11;
        unpack2(o0, r00, r01);
        unpack2(o1, r10, r11);
        if (mode == 0) {              // ELU (alpha=1)
            r00 = r00 > 0.f ? r00 : expm1f(r00);
            r01 = r01 > 0.f ? r01 : expm1f(r01);
            r10 = r10 > 0.f ? r10 : expm1f(r10);
            r11 = r11 > 0.f ? r11 : expm1f(r11);
        }
        int ia = i0 + il0;
        float2 xi0 = *(const float2*)&x_in[ia * DIM + col];
        float2 xi1 = *(const float2*)&x_in[(ia + 1) * DIM + col];
        *(float2*)&x_out[ia * DIM + col]       = make_float2(xi0.x + r00, xi0.y + r01);
        *(float2*)&x_out[(ia + 1) * DIM + col] = make_float2(xi1.x + r10, xi1.y + r11);
    }
}

// ---------------------------------------------------------------------------
extern "C" void kernel_launch(void* const* d_in, const int* in_sizes, int n_in,
                              void* d_out, int out_size) {
    const float* x   = (const float*)d_in[0];
    const int*   adj = (const int*)  d_in[1];
    const float* Wl0 = (const float*)d_in[2];
    const float* Wr0 = (const float*)d_in[3];
    const float* a0  = (const float*)d_in[4];
    const float* Wl1 = (const float*)d_in[5];
    const float* Wr1 = (const float*)d_in[6];
    const float* a1  = (const float*)d_in[7];
    float* out = (float*)d_out;

    dim3 gg(NH, NN / BM, 2);      // (8, 12, 2) — blockIdx.x = head
    dim3 ga(NN / TI, NH);         // (24, 8)

    // layer 0
    gemm_kernel<<<gg, 256>>>(x, Wl0, Wr0, a0, 0);
    attn_kernel<<<ga, 256>>>(a0, adj, x, out, 0);    // -> g_x1 (ELU + residual)
    // layer 1
    gemm_kernel<<<gg, 256>>>(x, Wl1, Wr1, a1, 1);
    attn_kernel<<<ga, 256>>>(a1, adj, x, out, 1);    // -> d_out (residual)
}